// round 16
// baseline (speedup 1.0000x reference)
#include <cuda_runtime.h>
#include <cuda_fp16.h>
#include <math.h>
#include <stdint.h>

#define NPTS 8192
#define DIM  256
#define BM 128
#define BN 128
#define BKC 64            // k-columns per chunk (f16), 128B rows
#define NCHUNK 4          // 256 / 64
#define NTILES 4          // column tiles per CTA

// dynamic smem (bytes): A0,A1,B0,B1 (16KB each) + aux
#define OFF_A0 0
#define OFF_A1 16384
#define OFF_B0 32768
#define OFF_B1 49152
#define OFF_AUX 65536     // c2s[128], s2s[2][128], rowP[128], colP[2][128]
#define SMEM_TOTAL (65536 + 3072)

#define LN2F 0.6931471805599453f
#define LOG2EF 1.4426950408889634f

static __device__ __half g_Cb[NPTS * DIM];
static __device__ __half g_Sb[NPTS * DIM];
static __device__ float g_c2[NPTS], g_s2[NPTS];
static __device__ float g_rowsum[NPTS], g_colsum[NPTS];

// ---------------------------------------------------------------------------
__device__ __forceinline__ uint32_t smem_u32(const void* p) {
    uint32_t a;
    asm("{.reg .u64 t; cvta.to.shared.u64 t, %1; cvt.u32.u64 %0, t;}" : "=r"(a) : "l"(p));
    return a;
}
__device__ __forceinline__ uint32_t swz(uint32_t x) { return x ^ ((x >> 3) & 0x70); }

__device__ __forceinline__ void cp16(uint32_t dst, const void* src) {
    asm volatile("cp.async.cg.shared.global [%0], [%1], 16;" :: "r"(dst), "l"(src));
}
__device__ __forceinline__ void ldsm4(uint32_t* r, uint32_t a) {
    asm volatile("ldmatrix.sync.aligned.m8n8.x4.shared.b16 {%0,%1,%2,%3}, [%4];"
                 : "=r"(r[0]), "=r"(r[1]), "=r"(r[2]), "=r"(r[3]) : "r"(a));
}
// f16 inputs, f16 accumulator
__device__ __forceinline__ void mma_f16(uint32_t* d, const uint32_t* a, const uint32_t* b) {
    asm volatile(
        "mma.sync.aligned.m16n8k16.row.col.f16.f16.f16.f16 "
        "{%0,%1}, {%2,%3,%4,%5}, {%6,%7}, {%0,%1};\n"
        : "+r"(d[0]), "+r"(d[1])
        : "r"(a[0]), "r"(a[1]), "r"(a[2]), "r"(a[3]), "r"(b[0]), "r"(b[1]));
}

// ---------------------------------------------------------------------------
// Prepass: f32 -> f16 copies, norms from the ROUNDED values, zero accums.
// ---------------------------------------------------------------------------
__global__ void dcl_prep_kernel(const float* __restrict__ C,
                                const float* __restrict__ S,
                                float* __restrict__ out) {
    int warp = threadIdx.x >> 5;
    int lane = threadIdx.x & 31;
    int row  = blockIdx.x * 8 + warp;

    if (lane == 0) { g_rowsum[row] = 0.0f; g_colsum[row] = 0.0f; }
    if (blockIdx.x == 0 && threadIdx.x == 0) out[0] = 0.0f;

    {
        const float4* src = (const float4*)(C + (size_t)row * DIM);
        float4 v0 = src[lane * 2], v1 = src[lane * 2 + 1];
        __half2 h0 = __floats2half2_rn(v0.x, v0.y), h1 = __floats2half2_rn(v0.z, v0.w);
        __half2 h2 = __floats2half2_rn(v1.x, v1.y), h3 = __floats2half2_rn(v1.z, v1.w);
        uint4 pk = make_uint4(*(uint32_t*)&h0, *(uint32_t*)&h1,
                              *(uint32_t*)&h2, *(uint32_t*)&h3);
        ((uint4*)(g_Cb + (size_t)row * DIM))[lane] = pk;
        float2 a = __half22float2(h0), b = __half22float2(h1);
        float2 c = __half22float2(h2), d = __half22float2(h3);
        float ss = a.x * a.x + a.y * a.y + b.x * b.x + b.y * b.y
                 + c.x * c.x + c.y * c.y + d.x * d.x + d.y * d.y;
#pragma unroll
        for (int m = 16; m >= 1; m >>= 1) ss += __shfl_xor_sync(0xffffffffu, ss, m);
        if (lane == 0) g_c2[row] = ss;
    }
    {
        const float4* src = (const float4*)(S + (size_t)row * DIM);
        float4 v0 = src[lane * 2], v1 = src[lane * 2 + 1];
        __half2 h0 = __floats2half2_rn(v0.x, v0.y), h1 = __floats2half2_rn(v0.z, v0.w);
        __half2 h2 = __floats2half2_rn(v1.x, v1.y), h3 = __floats2half2_rn(v1.z, v1.w);
        uint4 pk = make_uint4(*(uint32_t*)&h0, *(uint32_t*)&h1,
                              *(uint32_t*)&h2, *(uint32_t*)&h3);
        ((uint4*)(g_Sb + (size_t)row * DIM))[lane] = pk;
        float2 a = __half22float2(h0), b = __half22float2(h1);
        float2 c = __half22float2(h2), d = __half22float2(h3);
        float ss = a.x * a.x + a.y * a.y + b.x * b.x + b.y * b.y
                 + c.x * c.x + c.y * c.y + d.x * d.x + d.y * d.y;
#pragma unroll
        for (int m = 16; m >= 1; m >>= 1) ss += __shfl_xor_sync(0xffffffffu, ss, m);
        if (lane == 0) g_s2[row] = ss;
    }
}

// ---------------------------------------------------------------------------
// Main: f16 GEMM over 4 column tiles per CTA; epilogue of tile t-1 interleaved
// into the mainloop chunks of tile t (tensor/MUFU pipe overlap).
// grid = (16, 64), block = 256.
// ---------------------------------------------------------------------------
__global__ __launch_bounds__(256, 2)
void dcl_main_kernel(const float* __restrict__ T, float* __restrict__ out) {
    extern __shared__ char smem[];
    const uint32_t sb = smem_u32(smem);

    const int tid   = threadIdx.x;
    const int lane  = tid & 31;
    const int warp  = tid >> 5;
    const int warpM = warp & 1;        // 2 warps along M (64 rows)
    const int warpN = warp >> 1;       // 4 warps along N (32 cols)
    const int rowBase = blockIdx.y * BM;

    const int mrow  = lane & 7;
    const int matLo = (lane >> 3) & 1;
    const int matHi = (lane >> 4) & 1;
    const int g     = lane >> 2;
    const int tig   = lane & 3;

    float* aux    = (float*)(smem + OFF_AUX);
    float* c2s    = aux;            // 128
    float* s2sbuf = aux + 128;      // 2 x 128
    float* rowP   = aux + 384;      // 128
    float* colPbuf= aux + 512;      // 2 x 128
    if (tid < 128) { c2s[tid] = g_c2[rowBase + tid]; rowP[tid] = 0.0f; }

    const uint32_t aB[2] = { sb + OFF_A0, sb + OFF_A1 };
    const uint32_t bB[2] = { sb + OFF_B0, sb + OFF_B1 };
    const uint32_t aRowOff = (uint32_t)(warpM * 64 + matLo * 8 + mrow) * 128;
    const uint32_t bRowOff = (uint32_t)(warpN * 32 + matHi * 8 + mrow) * 128;

    const float kk = -__expf(T[0]) * LOG2EF;   // e = ex2(dist * kk)

    uint32_t acc[4][4][2], accO[4][4][2];
    float cAcc[8];
    float dloc = 0.0f;
    int oldColBase = 0;
    bool haveOld = false, oldDiag = false;

    auto fill = [&](int buf, int colBase, int ch) {
#pragma unroll
        for (int t2 = 0; t2 < 4; t2++) {
            int idx = tid + t2 * 256;
            int r = idx >> 3, gg = idx & 7;
            cp16(aB[buf] + swz((uint32_t)(r * 128 + gg * 16)),
                 g_Cb + (size_t)(rowBase + r) * DIM + ch * BKC + gg * 8);
        }
#pragma unroll
        for (int t2 = 0; t2 < 4; t2++) {
            int idx = tid + t2 * 256;
            int r = idx >> 3, gg = idx & 7;
            cp16(bB[buf] + swz((uint32_t)(r * 128 + gg * 16)),
                 g_Sb + (size_t)(colBase + r) * DIM + ch * BKC + gg * 8);
        }
        asm volatile("cp.async.commit_group;" ::: "memory");
    };

    // one quarter (mi = q) of the OLD tile's epilogue
    auto epi_quarter = [&](int q, const float* s2sO) {
        float rA0 = 0.0f, rA1 = 0.0f;
#pragma unroll
        for (int ni = 0; ni < 4; ni++) {
            float2 f01 = __half22float2(*(__half2*)&accO[q][ni][0]); // row g,   cols 2tig..+1
            float2 f23 = __half22float2(*(__half2*)&accO[q][ni][1]); // row g+8, cols 2tig..+1
            float accf[4] = { f01.x, f01.y, f23.x, f23.y };
#pragma unroll
            for (int c = 0; c < 4; c++) {
                const int h   = c >> 1;
                const int bb2 = c & 1;
                const int rl = warpM * 64 + q * 16 + g + h * 8;
                const int cl = warpN * 32 + ni * 8 + tig * 2 + bb2;
                float d2 = fmaxf(fmaf(-2.0f, accf[c], c2s[rl] + s2sO[cl]), 0.0f);
                float dist;
                asm("sqrt.approx.f32 %0, %1;" : "=f"(dist) : "f"(d2));
                float f = dist * kk;
                float e;
                asm("ex2.approx.f32 %0, %1;" : "=f"(e) : "f"(f));
                if (h) rA1 += e; else rA0 += e;
                cAcc[ni * 2 + bb2] += e;
                if (oldDiag && rl == cl) dloc += f;   // oldDiag => rowBase==oldColBase
            }
        }
        rA0 += __shfl_xor_sync(0xffffffffu, rA0, 1);
        rA0 += __shfl_xor_sync(0xffffffffu, rA0, 2);
        rA1 += __shfl_xor_sync(0xffffffffu, rA1, 1);
        rA1 += __shfl_xor_sync(0xffffffffu, rA1, 2);
        if (tig == 0) {
            atomicAdd(&rowP[warpM * 64 + q * 16 + g], rA0);
            atomicAdd(&rowP[warpM * 64 + q * 16 + 8 + g], rA1);
        }
    };

    auto finish_old = [&](float* colPO) {
#pragma unroll
        for (int j = 0; j < 8; j++) {
            float v = cAcc[j];
            v += __shfl_xor_sync(0xffffffffu, v, 4);
            v += __shfl_xor_sync(0xffffffffu, v, 8);
            v += __shfl_xor_sync(0xffffffffu, v, 16);
            if (g == 0) {
                int ni = j >> 1, bb2 = j & 1;
                atomicAdd(&colPO[warpN * 32 + ni * 8 + tig * 2 + bb2], v);
            }
        }
        if (oldDiag) {
            float d = dloc;
#pragma unroll
            for (int m = 16; m >= 1; m >>= 1)
                d += __shfl_xor_sync(0xffffffffu, d, m);
            if (lane == 0) atomicAdd(out, -d * (LN2F / (float)NPTS));
        }
        __syncthreads();
        if (tid < 128) atomicAdd(&g_colsum[oldColBase + tid], colPO[tid]);
    };

    for (int t = 0; t < NTILES; t++) {
        const int colBase = (blockIdx.x * NTILES + t) * BN;
        if (tid < 128) {
            s2sbuf[(t & 1) * 128 + tid] = g_s2[colBase + tid];
            colPbuf[(t & 1) * 128 + tid] = 0.0f;
        }
        const float* s2sO = s2sbuf + ((t & 1) ^ 1) * 128;
        float* colPO = colPbuf + ((t & 1) ^ 1) * 128;

        fill(0, colBase, 0);
        fill(1, colBase, 1);

#pragma unroll
        for (int mi = 0; mi < 4; mi++)
#pragma unroll
            for (int ni = 0; ni < 4; ni++) { acc[mi][ni][0] = 0u; acc[mi][ni][1] = 0u; }

#pragma unroll
        for (int ch = 0; ch < NCHUNK; ch++) {
            if (ch < NCHUNK - 1) asm volatile("cp.async.wait_group 1;" ::: "memory");
            else                 asm volatile("cp.async.wait_group 0;" ::: "memory");
            __syncthreads();

            const uint32_t ab = aB[ch & 1] + aRowOff;
            const uint32_t bb = bB[ch & 1] + bRowOff;

#pragma unroll
            for (int ks = 0; ks < 4; ks++) {
                const uint32_t ca = (uint32_t)((((ks << 1) | matHi) ^ mrow) << 4);
                const uint32_t cb = (uint32_t)((((ks << 1) | matLo) ^ mrow) << 4);
                uint32_t a[4][4], b[4][2];
#pragma unroll
                for (int mi = 0; mi < 4; mi++)
                    ldsm4(a[mi], ab + mi * 2048 + ca);
#pragma unroll
                for (int p = 0; p < 2; p++) {
                    uint32_t r[4];
                    ldsm4(r, bb + p * 2048 + cb);
                    b[2 * p][0] = r[0]; b[2 * p][1] = r[1];
                    b[2 * p + 1][0] = r[2]; b[2 * p + 1][1] = r[3];
                }
#pragma unroll
                for (int mi = 0; mi < 4; mi++)
#pragma unroll
                    for (int ni = 0; ni < 4; ni++)
                        mma_f16(acc[mi][ni], a[mi], b[ni]);
            }

            if (haveOld) epi_quarter(ch, s2sO);   // old tile's MUFU under new tile's HMMA

            if (ch + 2 < NCHUNK) {
                __syncthreads();
                fill(ch & 1, colBase, ch + 2);
            }
        }

        if (haveOld) finish_old(colPO);

        // promote current tile to "old"
#pragma unroll
        for (int mi = 0; mi < 4; mi++)
#pragma unroll
            for (int ni = 0; ni < 4; ni++) {
                accO[mi][ni][0] = acc[mi][ni][0];
                accO[mi][ni][1] = acc[mi][ni][1];
            }
#pragma unroll
        for (int j = 0; j < 8; j++) cAcc[j] = 0.0f;
        dloc = 0.0f;
        oldColBase = colBase;
        oldDiag = (rowBase == colBase);
        haveOld = true;
        __syncthreads();   // buffers reusable next tile
    }

    // final tile's epilogue (unoverlapped tail)
    {
        const float* s2sO = s2sbuf + ((NTILES - 1) & 1) * 128;
        float* colPO = colPbuf + ((NTILES - 1) & 1) * 128;
#pragma unroll
        for (int q = 0; q < 4; q++) epi_quarter(q, s2sO);
        finish_old(colPO);
    }

    __syncthreads();
    if (tid < 128) atomicAdd(&g_rowsum[rowBase + tid], rowP[tid]);
}

// ---------------------------------------------------------------------------
__global__ void dcl_final_kernel(float* __restrict__ out) {
    int i = blockIdx.x * blockDim.x + threadIdx.x;
    float v = logf(g_rowsum[i]) + logf(g_colsum[i]);
#pragma unroll
    for (int m = 16; m >= 1; m >>= 1) v += __shfl_xor_sync(0xffffffffu, v, m);
    if ((threadIdx.x & 31) == 0)
        atomicAdd(out, v * (0.5f / (float)NPTS));
}

// ---------------------------------------------------------------------------
extern "C" void kernel_launch(void* const* d_in, const int* in_sizes, int n_in,
                              void* d_out, int out_size) {
    const float* C = (const float*)d_in[0];
    const float* S = (const float*)d_in[1];
    const float* T = (const float*)d_in[2];
    float* out = (float*)d_out;

    static bool attr_set = false;
    if (!attr_set) {
        cudaFuncSetAttribute(dcl_main_kernel,
                             cudaFuncAttributeMaxDynamicSharedMemorySize, SMEM_TOTAL);
        attr_set = true;
    }

    dcl_prep_kernel<<<NPTS / 8, 256>>>(C, S, out);
    dim3 grid(NPTS / BN / NTILES, NPTS / BM);
    dcl_main_kernel<<<grid, 256, SMEM_TOTAL>>>(T, out);
    dcl_final_kernel<<<NPTS / 1024, 1024>>>(out);
}